// round 2
// baseline (speedup 1.0000x reference)
#include <cuda_runtime.h>
#include <math.h>
#include <float.h>

// Problem constants
#define N_      4
#define C_      21
#define H_      512
#define W_      512
#define HW      (H_*W_)
#define PH      171          // pooled spatial size: floor((512+2-3)/3)+1
#define PP      (PH*PH)      // 29241 pooled cells
#define NH      169          // PH - (radius-1)
#define M_      (NH*NH)      // 28561 samples per (n,c)
#define NC      (N_*C_)      // 84
#define ALPHA   5e-4
#define CLIPMIN 1e-6f
#define SPLIT   8
#define CHUNK   ((M_ + SPLIT - 1) / SPLIT)   // 3571
#define GRAMSZ  (NC*3*81)

// ------------------------- device scratch (static, allocation-free) --------
__device__ float  g_la[NC*PP];          // pooled one-hot labels (0/1)
__device__ float  g_pr[NC*PP];          // pooled probs (max sigmoid + 1e-6)
__device__ double g_gram[GRAMSZ];       // per (n,c): v0 la (45 tri + 9 sums),
                                        //            v1 pr (45 tri + 9 sums),
                                        //            v2 la x pr (81 full)
__device__ double g_bce;
__device__ double g_valid;
__device__ int    g_lab64;

// ------------------------- kernel 0: zero grams + init + dtype sniff -------
__global__ void k_init(const void* lab) {
    const int i = blockIdx.x * blockDim.x + threadIdx.x;
    if (i < GRAMSZ) g_gram[i] = 0.0;
    if (i == 0) {
        // int64 labels (<21) have zero high words at odd int32 positions.
        const int* p = (const int*)lab;
        bool is64 = true;
        #pragma unroll 1
        for (int k = 0; k < 64; k++)
            if (p[2*k + 1] != 0) { is64 = false; break; }
        g_lab64 = is64 ? 1 : 0;
        g_bce   = 0.0;
        g_valid = 0.0;
    }
}

// ------------------------- kernel 1: fused max-pool + BCE ------------------
// One thread per pooled cell per batch. Windows (k=3,s=3,pad=1) partition the
// image, so per-pixel BCE is accumulated exactly once.
// Tricks: sum_c softplus(x_c) = sum_c relu(x_c) + log(prod_c (1 + e^{-|x_c|}))
//         max-pool(sigmoid) = sigmoid(max-pool(logit))  (monotone)
__global__ void __launch_bounds__(128)
k_pool_bce(const float* __restrict__ logits, const void* __restrict__ labv) {
    const int p = blockIdx.x * blockDim.x + threadIdx.x;
    const int n = blockIdx.y;

    float bce_acc = 0.f;
    int   valid   = 0;

    if (p < PP) {
        const int i  = p / PH, j = p - i * PH;
        const int y0 = 3*i - 1, x0 = 3*j - 1;

        const bool is64 = (g_lab64 != 0);
        const long long* L64 = (const long long*)labv;
        const int*       L32 = (const int*)labv;
        const float* __restrict__ base = logits + (size_t)n * C_ * HW;

        float maxl[C_];
        #pragma unroll
        for (int c = 0; c < C_; c++) maxl[c] = -FLT_MAX;
        unsigned labmask = 0u;

        #pragma unroll 1
        for (int dy = 0; dy < 3; dy++) {
            const int y = y0 + dy;
            if (y < 0 || y >= H_) continue;
            #pragma unroll 1
            for (int dx = 0; dx < 3; dx++) {
                const int x = x0 + dx;
                if (x < 0 || x >= W_) continue;
                const int pix = (n*H_ + y)*W_ + x;
                const int lv  = is64 ? (int)L64[pix] : L32[pix];
                if ((unsigned)lv >= (unsigned)C_) continue;   // masked pixel
                valid++;
                labmask |= (1u << lv);
                const float* __restrict__ px = base + y*W_ + x;

                float prod = 1.f;   // prod of (1 + e^{-|x_c|})
                float racc = 0.f;   // sum of relu(x_c)
                #pragma unroll
                for (int c = 0; c < C_; c++) {
                    const float xv = px[(size_t)c * HW];
                    maxl[c] = fmaxf(maxl[c], xv);
                    const float t = __expf(-fabsf(xv));
                    prod = fmaf(prod, t, prod);
                    racc += fmaxf(xv, 0.f);
                }
                bce_acc += racc + __logf(prod);
                bce_acc -= px[(size_t)lv * HW];   // - y*x (one-hot), L1 hit
            }
        }

        // emit pooled one-hot labels + pooled probs (single sigmoid per class)
        const int ncbase = n * C_;
        const bool anyv = (valid > 0);
        #pragma unroll
        for (int c = 0; c < C_; c++) {
            float sg = 0.f;
            if (anyv) {
                const float m = maxl[c];
                const float t = __expf(-fabsf(m));
                const float u = __fdividef(1.f, 1.f + t);
                sg = (m >= 0.f) ? u : t * u;
            }
            g_pr[(ncbase + c)*PP + p] = sg + CLIPMIN;
            g_la[(ncbase + c)*PP + p] = (labmask >> c) & 1u ? 1.f : 0.f;
        }
    }

    // block reduce (double) -> atomic
    double b = (double)bce_acc;
    double v = (double)valid;
    #pragma unroll
    for (int o = 16; o > 0; o >>= 1) {
        b += __shfl_down_sync(0xffffffffu, b, o);
        v += __shfl_down_sync(0xffffffffu, v, o);
    }
    __shared__ double sb[4], sv[4];
    const int lane = threadIdx.x & 31, wid = threadIdx.x >> 5;
    if (lane == 0) { sb[wid] = b; sv[wid] = v; }
    __syncthreads();
    if (threadIdx.x == 0) {
        atomicAdd(&g_bce,   sb[0] + sb[1] + sb[2] + sb[3]);
        atomicAdd(&g_valid, sv[0] + sv[1] + sv[2] + sv[3]);
    }
}

// ------------------------- kernel 2: 9x9 Gram matrices (merged, split) -----
__device__ __forceinline__ void reduce_atomic(const float* acc, int nacc,
                                              double* out, double (*smem)[81]) {
    const int lane = threadIdx.x & 31, wid = threadIdx.x >> 5;
    #pragma unroll
    for (int k = 0; k < 81; k++) {
        if (k >= nacc) break;
        double x = (double)acc[k];
        #pragma unroll
        for (int o = 16; o > 0; o >>= 1) x += __shfl_down_sync(0xffffffffu, x, o);
        if (lane == 0) smem[wid][k] = x;
    }
    __syncthreads();
    for (int k = threadIdx.x; k < nacc; k += 256) {
        double s = 0.0;
        #pragma unroll
        for (int w = 0; w < 8; w++) s += smem[w][k];
        atomicAdd(&out[k], s);
    }
}

__global__ void __launch_bounds__(256)
k_gram_all() {
    __shared__ double smem[8][81];
    const int nc = blockIdx.x;
    const int v  = blockIdx.z;
    const int m0 = blockIdx.y * CHUNK;
    const int m1 = (m0 + CHUNK < M_) ? m0 + CHUNK : M_;
    double* out = g_gram + (size_t)(nc*3 + v) * 81;

    if (v == 2) {
        const float* __restrict__ A = g_la + (size_t)nc * PP;
        const float* __restrict__ B = g_pr + (size_t)nc * PP;
        float acc[81];
        #pragma unroll
        for (int k = 0; k < 81; k++) acc[k] = 0.f;
        for (int m = m0 + threadIdx.x; m < m1; m += 256) {
            const int i = m / NH, j = m - i * NH;
            const float* pa = A + i*PH + j;
            const float* pb = B + i*PH + j;
            float a[9], bb[9];
            #pragma unroll
            for (int d = 0; d < 9; d++) a[d]  = pa[(d/3)*PH + (d%3)];
            #pragma unroll
            for (int d = 0; d < 9; d++) bb[d] = pb[(d/3)*PH + (d%3)];
            #pragma unroll
            for (int d = 0; d < 9; d++)
                #pragma unroll
                for (int e = 0; e < 9; e++)
                    acc[d*9 + e] += a[d] * bb[e];
        }
        reduce_atomic(acc, 81, out, smem);
    } else {
        const float* __restrict__ A = ((v == 1) ? g_pr : g_la) + (size_t)nc * PP;
        float acc[54];
        #pragma unroll
        for (int k = 0; k < 54; k++) acc[k] = 0.f;
        for (int m = m0 + threadIdx.x; m < m1; m += 256) {
            const int i = m / NH, j = m - i * NH;
            const float* pa = A + i*PH + j;
            float a[9];
            #pragma unroll
            for (int d = 0; d < 9; d++) a[d] = pa[(d/3)*PH + (d%3)];
            int k = 0;
            #pragma unroll
            for (int d = 0; d < 9; d++)
                #pragma unroll
                for (int e = d; e < 9; e++)
                    acc[k++] += a[d] * a[e];
            #pragma unroll
            for (int d = 0; d < 9; d++) acc[45 + d] += a[d];
        }
        reduce_atomic(acc, 54, out, smem);
    }
}

// ------------------------- kernel 3: per-(n,c) linear algebra + combine ----
__global__ void __launch_bounds__(128)
k_finalize(float* __restrict__ outp) {
    __shared__ double ssum[128];
    const int t = threadIdx.x;
    double rmi = 0.0;

    if (t < NC) {
        const double* G0 = g_gram + (size_t)(t*3 + 0)*81;  // la
        const double* G1 = g_gram + (size_t)(t*3 + 1)*81;  // pr
        const double* G2 = g_gram + (size_t)(t*3 + 2)*81;  // la x pr

        double Sla[9], Spr[9];
        for (int d = 0; d < 9; d++) { Sla[d] = G0[45+d]; Spr[d] = G1[45+d]; }
        const double invM = 1.0 / (double)M_;

        double Cla[9][9], P[9][9], Bm[9][9];
        {
            int k = 0;
            for (int d = 0; d < 9; d++)
                for (int e = d; e < 9; e++) {
                    const double cl = G0[k] - Sla[d]*Sla[e]*invM;
                    const double cp = G1[k] - Spr[d]*Spr[e]*invM;
                    Cla[d][e] = Cla[e][d] = cl;
                    P[d][e]   = P[e][d]   = cp;
                    k++;
                }
            for (int d = 0; d < 9; d++) P[d][d] += ALPHA;
            for (int d = 0; d < 9; d++)
                for (int e = 0; e < 9; e++)
                    Bm[d][e] = G2[d*9 + e] - Sla[d]*Spr[e]*invM;
        }

        // Cholesky of P = L L^T
        double Lm[9][9];
        for (int a = 0; a < 9; a++) {
            for (int b = 0; b <= a; b++) {
                double s = P[a][b];
                for (int c = 0; c < b; c++) s -= Lm[a][c]*Lm[b][c];
                if (a == b) Lm[a][a] = sqrt(fmax(s, 1e-300));
                else        Lm[a][b] = s / Lm[b][b];
            }
        }
        // W = B L^{-T}  (row-wise forward substitution)
        double Wm[9][9];
        for (int d = 0; d < 9; d++)
            for (int e = 0; e < 9; e++) {
                double s = Bm[d][e];
                for (int k = 0; k < e; k++) s -= Wm[d][k]*Lm[e][k];
                Wm[d][e] = s / Lm[e][e];
            }
        // A2 = Cla - W W^T + alpha I
        double A2[9][9];
        for (int d = 0; d < 9; d++)
            for (int g = 0; g < 9; g++) {
                double s = 0.0;
                for (int k = 0; k < 9; k++) s += Wm[d][k]*Wm[g][k];
                A2[d][g] = Cla[d][g] - s;
            }
        for (int d = 0; d < 9; d++) A2[d][d] += ALPHA;
        // Cholesky of A2; rmi = sum log(diag + 1e-8)
        double sum = 0.0;
        for (int a = 0; a < 9; a++) {
            for (int b = 0; b <= a; b++) {
                double s = A2[a][b];
                for (int c = 0; c < b; c++) s -= Lm[a][c]*Lm[b][c];
                if (a == b) {
                    const double dv = sqrt(fmax(s, 1e-300));
                    Lm[a][a] = dv;
                    sum += log(dv + 1e-8);
                } else {
                    Lm[a][b] = s / Lm[b][b];
                }
            }
        }
        rmi = sum;
    }

    ssum[t] = rmi;
    __syncthreads();
    for (int s = 64; s > 0; s >>= 1) {
        if (t < s) ssum[t] += ssum[t + s];
        __syncthreads();
    }
    if (t == 0) {
        const double rmi_total = ssum[0] / (double)(N_ * 9);
        const double bce_loss  = g_bce / (g_valid + 1.0);
        outp[0] = (float)(0.5 * bce_loss + 0.5 * rmi_total);
    }
}

// ------------------------- launch ------------------------------------------
extern "C" void kernel_launch(void* const* d_in, const int* in_sizes, int n_in,
                              void* d_out, int out_size) {
    const float* logits = (const float*)d_in[0];
    const void*  labels = d_in[1];

    k_init<<<(GRAMSZ + 255) / 256, 256>>>(labels);
    dim3 g1((PP + 127) / 128, N_);
    k_pool_bce<<<g1, 128>>>(logits, labels);
    dim3 g2(NC, SPLIT, 3);
    k_gram_all<<<g2, 256>>>();
    k_finalize<<<1, 128>>>((float*)d_out);
}

// round 3
// speedup vs baseline: 1.1695x; 1.1695x over previous
#include <cuda_runtime.h>
#include <math.h>
#include <float.h>

#define N_      4
#define C_      21
#define H_      512
#define W_      512
#define HW      (H_*W_)
#define PH      171
#define PP      (PH*PH)      // 29241
#define NH      169
#define M_      (NH*NH)      // 28561
#define NC      (N_*C_)      // 84
#define ALPHA   5e-4
#define CLIPMIN 1e-6f
#define SPLIT   8
#define CHUNK   ((M_ + SPLIT - 1) / SPLIT)
#define GRAMSZ  (NC*3*81)
#define FULLM   0xffffffffu

// ------------------------- device scratch ----------------------------------
__device__ float  g_la[NC*PP];
__device__ float  g_pr[NC*PP];
__device__ double g_gram[GRAMSZ];
__device__ double g_bce;
__device__ double g_valid;
__device__ double g_rmi;
__device__ int    g_lab64;

// ------------------------- kernel 0: zero + dtype sniff --------------------
__global__ void k_init(const void* lab) {
    const int i = blockIdx.x * blockDim.x + threadIdx.x;
    if (i < GRAMSZ) g_gram[i] = 0.0;
    if (i == 0) {
        const int* p = (const int*)lab;
        bool is64 = true;
        #pragma unroll 1
        for (int k = 0; k < 64; k++)
            if (p[2*k + 1] != 0) { is64 = false; break; }
        g_lab64 = is64 ? 1 : 0;
        g_bce = 0.0; g_valid = 0.0; g_rmi = 0.0;
    }
}

// ------------------------- kernel 1: fused max-pool + BCE ------------------
__global__ void __launch_bounds__(256)
k_pool_bce(const float* __restrict__ logits, const void* __restrict__ labv) {
    const int p = blockIdx.x * blockDim.x + threadIdx.x;
    const int n = blockIdx.y;

    float bce_acc = 0.f;
    int   valid   = 0;

    if (p < PP) {
        const int i  = p / PH, j = p - i * PH;
        const int y0 = 3*i - 1, x0 = 3*j - 1;

        const bool is64 = (g_lab64 != 0);
        const long long* L64 = (const long long*)labv;
        const int*       L32 = (const int*)labv;

        // positional 9-slot window: compile-time indices only
        int offk[9], labk[9];
        unsigned vmask = 0, labmask = 0;
        #pragma unroll
        for (int ky = 0; ky < 3; ky++) {
            #pragma unroll
            for (int kx = 0; kx < 3; kx++) {
                const int s = ky*3 + kx;
                const int y = y0 + ky, x = x0 + kx;
                const bool inb = ((unsigned)y < H_) && ((unsigned)x < W_);
                const int pix = inb ? (y*W_ + x) : 0;
                const int gidx = n*HW + pix;
                const int lv = inb ? (is64 ? (int)L64[gidx] : L32[gidx]) : -1;
                const bool val = inb && ((unsigned)lv < (unsigned)C_);
                offk[s] = pix;
                labk[s] = val ? lv : -1;
                if (val) { vmask |= (1u << s); valid++; labmask |= (1u << lv); }
            }
        }

        const float* __restrict__ base = logits + (size_t)n * C_ * HW;
        const int ncbase = n * C_;

        #pragma unroll 1
        for (int c = 0; c < C_; c++) {
            const float* __restrict__ px = base + (size_t)c * HW;
            float maxv = -FLT_MAX;
            float prod = 1.f;      // prod over window of (1 + e^{-|x|})
            float racc = 0.f;      // sum relu(x) - onehot*x
            #pragma unroll
            for (int k = 0; k < 9; k++) {
                float xv = px[offk[k]];
                xv = ((vmask >> k) & 1u) ? xv : -FLT_MAX;  // neutral element
                maxv = fmaxf(maxv, xv);
                const float t = __expf(-fabsf(xv));        // 0 for invalid
                prod = fmaf(prod, t, prod);
                racc += fmaxf(xv, 0.f);
                racc -= (labk[k] == c) ? xv : 0.f;
            }
            bce_acc += racc + __logf(prod);
            // pooled prob = sigmoid(max logit) (monotone), 0 if no valid pixel
            float sg = 0.f;
            if (vmask) {
                const float t = __expf(-fabsf(maxv));
                const float u = __fdividef(1.f, 1.f + t);
                sg = (maxv >= 0.f) ? u : t * u;
            }
            g_pr[(ncbase + c)*PP + p] = sg + CLIPMIN;
            g_la[(ncbase + c)*PP + p] = ((labmask >> c) & 1u) ? 1.f : 0.f;
        }
    }

    // block reduce -> atomic
    double b = (double)bce_acc, v = (double)valid;
    #pragma unroll
    for (int o = 16; o > 0; o >>= 1) {
        b += __shfl_down_sync(FULLM, b, o);
        v += __shfl_down_sync(FULLM, v, o);
    }
    __shared__ double sb[8], sv[8];
    const int lane = threadIdx.x & 31, wid = threadIdx.x >> 5;
    if (lane == 0) { sb[wid] = b; sv[wid] = v; }
    __syncthreads();
    if (threadIdx.x == 0) {
        double tb = 0, tv = 0;
        #pragma unroll
        for (int w = 0; w < 8; w++) { tb += sb[w]; tv += sv[w]; }
        atomicAdd(&g_bce, tb);
        atomicAdd(&g_valid, tv);
    }
}

// ------------------------- kernel 2: 9x9 Grams (merged, M-split) -----------
template<int NACC>
__device__ __forceinline__ void reduce_atomic(const float* acc, double* out,
                                              double (*smem)[81]) {
    const int lane = threadIdx.x & 31, wid = threadIdx.x >> 5;
    #pragma unroll
    for (int k = 0; k < NACC; k++) {
        double x = (double)acc[k];
        #pragma unroll
        for (int o = 16; o > 0; o >>= 1) x += __shfl_down_sync(FULLM, x, o);
        if (lane == 0) smem[wid][k] = x;
    }
    __syncthreads();
    for (int k = threadIdx.x; k < NACC; k += 256) {
        double s = 0.0;
        #pragma unroll
        for (int w = 0; w < 8; w++) s += smem[w][k];
        atomicAdd(&out[k], s);
    }
}

__global__ void __launch_bounds__(256)
k_gram_all() {
    __shared__ double smem[8][81];
    const int nc = blockIdx.x;
    const int v  = blockIdx.z;
    const int m0 = blockIdx.y * CHUNK;
    const int m1 = (m0 + CHUNK < M_) ? m0 + CHUNK : M_;
    double* out = g_gram + (size_t)(nc*3 + v) * 81;

    if (v == 2) {
        const float* __restrict__ A = g_la + (size_t)nc * PP;
        const float* __restrict__ B = g_pr + (size_t)nc * PP;
        float acc[81];
        #pragma unroll
        for (int k = 0; k < 81; k++) acc[k] = 0.f;
        for (int m = m0 + threadIdx.x; m < m1; m += 256) {
            const int i = m / NH, j = m - i * NH;
            const float* pa = A + i*PH + j;
            const float* pb = B + i*PH + j;
            float a[9], bb[9];
            #pragma unroll
            for (int d = 0; d < 9; d++) a[d]  = pa[(d/3)*PH + (d%3)];
            #pragma unroll
            for (int d = 0; d < 9; d++) bb[d] = pb[(d/3)*PH + (d%3)];
            #pragma unroll
            for (int d = 0; d < 9; d++)
                #pragma unroll
                for (int e = 0; e < 9; e++)
                    acc[d*9 + e] += a[d] * bb[e];
        }
        reduce_atomic<81>(acc, out, smem);
    } else {
        const float* __restrict__ A = ((v == 1) ? g_pr : g_la) + (size_t)nc * PP;
        float acc[54];
        #pragma unroll
        for (int k = 0; k < 54; k++) acc[k] = 0.f;
        for (int m = m0 + threadIdx.x; m < m1; m += 256) {
            const int i = m / NH, j = m - i * NH;
            const float* pa = A + i*PH + j;
            float a[9];
            #pragma unroll
            for (int d = 0; d < 9; d++) a[d] = pa[(d/3)*PH + (d%3)];
            int k = 0;
            #pragma unroll
            for (int d = 0; d < 9; d++)
                #pragma unroll
                for (int e = d; e < 9; e++)
                    acc[k++] += a[d] * a[e];
            #pragma unroll
            for (int d = 0; d < 9; d++) acc[45 + d] += a[d];
        }
        reduce_atomic<54>(acc, out, smem);
    }
}

// ------------------------- kernel 3: warp-parallel linear algebra ----------
// One block (32 threads) per (n,c). Lane d (d<9) holds row d of each 9x9
// matrix in registers; columns broadcast via shfl. No local-memory spills.
__global__ void __launch_bounds__(32)
k_finalize() {
    const int nc = blockIdx.x;
    const int d  = threadIdx.x;
    const int dd = (d < 9) ? d : 0;           // inactive lanes mirror row 0

    const double* __restrict__ G0 = g_gram + (size_t)(nc*3 + 0)*81;
    const double* __restrict__ G1 = g_gram + (size_t)(nc*3 + 1)*81;
    const double* __restrict__ G2 = g_gram + (size_t)(nc*3 + 2)*81;

    const double invM = 1.0 / (double)M_;
    const double sla_d = G0[45 + dd], spr_d = G1[45 + dd];

    double Cr[9], Pr[9], Br[9];
    #pragma unroll
    for (int e = 0; e < 9; e++) {
        const int lo = (dd < e) ? dd : e;
        const int hi = (dd < e) ? e : dd;
        const int tri = lo*9 - (lo*(lo-1))/2 + (hi - lo);
        const double sla_e = G0[45 + e], spr_e = G1[45 + e];
        Cr[e] = G0[tri] - sla_d*sla_e*invM + ((e == dd) ? ALPHA : 0.0);
        Pr[e] = G1[tri] - spr_d*spr_e*invM + ((e == dd) ? ALPHA : 0.0);
        Br[e] = G2[dd*9 + e] - sla_d*spr_e*invM;
    }

    // Cholesky of P: lane d ends with Lr[k] = L[d][k] (valid for d >= k)
    double Lr[9];
    #pragma unroll
    for (int k = 0; k < 9; k++) {
        const double pkk = __shfl_sync(FULLM, Pr[k], k);
        const double lkk = sqrt(fmax(pkk, 1e-300));
        const double ldk = Pr[k] * (1.0 / lkk);
        Lr[k] = ldk;
        #pragma unroll
        for (int j = 0; j < 9; j++)
            if (j > k) Pr[j] -= ldk * __shfl_sync(FULLM, ldk, j);
    }

    // W = B L^{-T}: column-sequential forward substitution
    double Wr[9];
    #pragma unroll
    for (int e = 0; e < 9; e++) {
        double s = Br[e];
        #pragma unroll
        for (int k = 0; k < 9; k++)
            if (k < e) s -= Wr[k] * __shfl_sync(FULLM, Lr[k], e);
        const double lee = __shfl_sync(FULLM, Lr[e], e);
        Wr[e] = s * (1.0 / lee);
    }

    // A2 = Cla + alpha I - W W^T  (into Cr)
    #pragma unroll
    for (int e = 0; e < 9; e++) {
        double s = 0.0;
        #pragma unroll
        for (int k = 0; k < 9; k++)
            s += Wr[k] * __shfl_sync(FULLM, Wr[k], e);
        Cr[e] -= s;
    }

    // Cholesky of A2; accumulate sum log(diag + 1e-8)
    double lsum = 0.0;
    #pragma unroll
    for (int k = 0; k < 9; k++) {
        const double akk = __shfl_sync(FULLM, Cr[k], k);
        const double lkk = sqrt(fmax(akk, 1e-300));
        lsum += log(lkk + 1e-8);
        const double ldk = Cr[k] * (1.0 / lkk);
        #pragma unroll
        for (int j = 0; j < 9; j++)
            if (j > k) Cr[j] -= ldk * __shfl_sync(FULLM, ldk, j);
    }

    if (d == 0) atomicAdd(&g_rmi, lsum);
}

// ------------------------- kernel 4: combine --------------------------------
__global__ void k_out(float* __restrict__ outp) {
    const double rmi_total = g_rmi / (double)(N_ * 9);
    const double bce_loss  = g_bce / (g_valid + 1.0);
    outp[0] = (float)(0.5 * bce_loss + 0.5 * rmi_total);
}

// ------------------------- launch ------------------------------------------
extern "C" void kernel_launch(void* const* d_in, const int* in_sizes, int n_in,
                              void* d_out, int out_size) {
    const float* logits = (const float*)d_in[0];
    const void*  labels = d_in[1];

    k_init<<<(GRAMSZ + 255) / 256, 256>>>(labels);
    dim3 g1((PP + 255) / 256, N_);
    k_pool_bce<<<g1, 256>>>(logits, labels);
    dim3 g2(NC, SPLIT, 3);
    k_gram_all<<<g2, 256>>>();
    k_finalize<<<NC, 32>>>();
    k_out<<<1, 1>>>((float*)d_out);
}